// round 13
// baseline (speedup 1.0000x reference)
#include <cuda_runtime.h>

// out[b, s, d] = x[b, s, d] - sum_d' x[b, s, d']
// x: (8, 8192, 512) fp32 -> 65536 rows of 512 floats.
// R10: persistent grid (one wave, 3 blocks/SM x 152 SMs) + 2-stage software
// pipeline: each warp grid-strides over rows, issuing the NEXT row's 4 loads
// before the current row's shuffle-reduce + store. Eliminates ~13 wave
// transitions and keeps a full row of loads in flight during the reduction
// latency. Memory scheme unchanged (float4 + streaming hints = best measured).

static constexpr int D = 512;
static constexpr int VEC_PER_ROW = D / 4;              // 128 float4 per row
static constexpr int VEC_PER_LANE = VEC_PER_ROW / 32;  // 4
static constexpr int N_ROWS = 65536;

__device__ __forceinline__ void load_row(const float4* __restrict__ x,
                                         int row_idx, int lane, float4 v[VEC_PER_LANE]) {
    const float4* row = x + (size_t)row_idx * VEC_PER_ROW;
#pragma unroll
    for (int i = 0; i < VEC_PER_LANE; i++)
        v[i] = __ldcs(&row[lane + 32 * i]);
}

__device__ __forceinline__ void reduce_store(float4* __restrict__ out,
                                             int row_idx, int lane,
                                             float4 v[VEC_PER_LANE]) {
    float s = 0.0f;
#pragma unroll
    for (int i = 0; i < VEC_PER_LANE; i++)
        s += (v[i].x + v[i].y) + (v[i].z + v[i].w);
#pragma unroll
    for (int off = 16; off > 0; off >>= 1)
        s += __shfl_xor_sync(0xffffffffu, s, off);

    float4* orow = out + (size_t)row_idx * VEC_PER_ROW;
#pragma unroll
    for (int i = 0; i < VEC_PER_LANE; i++) {
        float4 r = v[i];
        r.x -= s; r.y -= s; r.z -= s; r.w -= s;
        __stcs(&orow[lane + 32 * i], r);
    }
}

__global__ void __launch_bounds__(512)
row_center_kernel(const float4* __restrict__ x, float4* __restrict__ out,
                  int n_warps_total) {
    const int warp_id = (blockIdx.x * blockDim.x + threadIdx.x) >> 5;
    const int lane = threadIdx.x & 31;

    // Each warp handles rows warp_id, warp_id + stride, ...
    const int stride = n_warps_total;

    int r = warp_id;
    if (r >= N_ROWS) return;

    float4 cur[VEC_PER_LANE], nxt[VEC_PER_LANE];
    load_row(x, r, lane, cur);

    for (int rn = r + stride; rn < N_ROWS; rn += stride) {
        load_row(x, rn, lane, nxt);        // next row's loads in flight...
        reduce_store(out, r, lane, cur);   // ...during this row's reduction
#pragma unroll
        for (int i = 0; i < VEC_PER_LANE; i++) cur[i] = nxt[i];
        r = rn;
    }
    reduce_store(out, r, lane, cur);
}

extern "C" void kernel_launch(void* const* d_in, const int* in_sizes, int n_in,
                              void* d_out, int out_size) {
    const float* x = (const float*)d_in[0];
    float* out = (float*)d_out;

    const int threads = 512;                     // 16 warps/block
    const int blocks = 456;                      // 3 per SM x 152 SMs, one wave
    const int n_warps_total = blocks * (threads / 32);  // 7296 warps

    row_center_kernel<<<blocks, threads>>>(
        (const float4*)x, (float4*)out, n_warps_total);
}

// round 14
// speedup vs baseline: 1.0646x; 1.0646x over previous
#include <cuda_runtime.h>

// out[b, s, d] = x[b, s, d] - sum_d' x[b, s, d']
// x: (8, 8192, 512) fp32 -> 65536 rows of 512 floats.
//
// FINAL (converged) kernel = R8 champion, 43.5us.
// Evidence of convergence: compulsory traffic 268 MB at measured ~5.9 TB/s
// mixed-stream DRAM ceiling -> ~36us kernel floor, which this kernel hits.
// Probed and rejected: L2 evict hints (x3 variants, neutral/worse), higher
// per-warp MLP (neutral), 256-bit accesses (neutral), 1024-thread CTAs
// (flat), persistent+pipelined grid (regressed via register pressure).
// Winning config: warp-per-row, register-resident float4, streaming
// load/store, 512-thread CTAs, exact 4096-block grid (29 regs, 0 smem).

static constexpr int D = 512;
static constexpr int VEC_PER_ROW = D / 4;              // 128 float4 per row
static constexpr int VEC_PER_LANE = VEC_PER_ROW / 32;  // 4

__global__ void __launch_bounds__(512)
row_center_kernel(const float4* __restrict__ x, float4* __restrict__ out) {
    const int warp_global = (blockIdx.x * blockDim.x + threadIdx.x) >> 5;
    const int lane = threadIdx.x & 31;

    const float4* __restrict__ row = x + (size_t)warp_global * VEC_PER_ROW;
    float4* __restrict__ orow = out + (size_t)warp_global * VEC_PER_ROW;

    float4 v[VEC_PER_LANE];
    float s = 0.0f;
#pragma unroll
    for (int i = 0; i < VEC_PER_LANE; i++) {
        v[i] = __ldcs(&row[lane + 32 * i]);
        s += (v[i].x + v[i].y) + (v[i].z + v[i].w);
    }

    // warp tree reduction
#pragma unroll
    for (int off = 16; off > 0; off >>= 1)
        s += __shfl_xor_sync(0xffffffffu, s, off);

#pragma unroll
    for (int i = 0; i < VEC_PER_LANE; i++) {
        float4 r = v[i];
        r.x -= s; r.y -= s; r.z -= s; r.w -= s;
        __stcs(&orow[lane + 32 * i], r);
    }
}

extern "C" void kernel_launch(void* const* d_in, const int* in_sizes, int n_in,
                              void* d_out, int out_size) {
    const float* x = (const float*)d_in[0];
    float* out = (float*)d_out;
    const int n_rows = in_sizes[0] / D;          // 65536
    const int threads = 512;                     // 16 warps/block
    const int blocks = n_rows / (threads / 32);  // 4096, exact

    row_center_kernel<<<blocks, threads>>>(
        (const float4*)x, (float4*)out);
}